// round 9
// baseline (speedup 1.0000x reference)
#include <cuda_runtime.h>
#include <cuda_fp16.h>
#include <math.h>

// ---------------- Problem constants ----------------
#define S_LEN 2048
#define D_MOD 768
#define N_HEADS 12
#define HDIM 64
#define QT 64
#define KW 192

// ---------------- fp16 GEMM constants ----------------
#define GK 768
#define NCHUNK 12          // GK / 64
#define CHUNK_K 64

// ---------------- Scratch (no cudaMalloc allowed) ----------------
__device__ float g_Q[S_LEN * D_MOD];
__device__ float g_K[S_LEN * D_MOD];
__device__ float g_V[S_LEN * D_MOD];
__device__ float g_ctx[S_LEN * D_MOD];
__device__ __align__(1024) __half g_Apk[3][S_LEN * GK];
__device__ __align__(1024) __half g_Bpk[3][D_MOD * GK];

// ---------------- PTX helpers (base sm_103-safe: sm_80 era) ----------------
__device__ __forceinline__ unsigned smem_u32(const void* p) {
    unsigned a;
    asm("{ .reg .u64 t; cvta.to.shared.u64 t, %1; cvt.u32.u64 %0, t; }"
        : "=r"(a) : "l"(p));
    return a;
}
__device__ __forceinline__ void cp_async16(unsigned saddr, const void* gptr) {
    asm volatile("cp.async.cg.shared.global [%0], [%1], 16;"
                 :: "r"(saddr), "l"(gptr));
}
__device__ __forceinline__ void cp_commit() {
    asm volatile("cp.async.commit_group;");
}
__device__ __forceinline__ void cp_wait1() {
    asm volatile("cp.async.wait_group 1;");
}
__device__ __forceinline__ void ldsm_x4(unsigned* r, unsigned addr) {
    asm volatile("ldmatrix.sync.aligned.m8n8.x4.shared.b16 {%0,%1,%2,%3}, [%4];"
                 : "=r"(r[0]), "=r"(r[1]), "=r"(r[2]), "=r"(r[3]) : "r"(addr));
}
__device__ __forceinline__ void mma16816(float* c, const unsigned* a, const unsigned* b) {
    asm volatile(
        "mma.sync.aligned.m16n8k16.row.col.f32.f16.f16.f32 "
        "{%0,%1,%2,%3}, {%4,%5,%6,%7}, {%8,%9}, {%0,%1,%2,%3};"
        : "+f"(c[0]), "+f"(c[1]), "+f"(c[2]), "+f"(c[3])
        : "r"(a[0]), "r"(a[1]), "r"(a[2]), "r"(a[3]), "r"(b[0]), "r"(b[1]));
}
__device__ __forceinline__ unsigned packh2(__half a, __half b) {
    __half2 t = __halves2half2(a, b);
    return *(unsigned*)&t;
}

// ---------------------------------------------------------------------------
// Pack A (up to 3 inputs): fp32 [2048x768] -> fp16 [2048][768]
// ---------------------------------------------------------------------------
__global__ __launch_bounds__(256) void pack_A3_kernel(
    const float* __restrict__ A0, const float* __restrict__ A1,
    const float* __restrict__ A2,
    __half* __restrict__ O0, __half* __restrict__ O1, __half* __restrict__ O2)
{
    const int z = blockIdx.y;
    const float* A = (z == 0) ? A0 : (z == 1) ? A1 : A2;
    __half* O = (z == 0) ? O0 : (z == 1) ? O1 : O2;

    int g = blockIdx.x * 256 + threadIdx.x;     // < 2048*192
    int idx4 = g * 4;
    float4 v = *(const float4*)&A[idx4];
    uint2 hw = make_uint2(packh2(__float2half(v.x), __float2half(v.y)),
                          packh2(__float2half(v.z), __float2half(v.w)));
    *(uint2*)&O[idx4] = hw;
}

// ---------------------------------------------------------------------------
// Pack W (up to 3 weights): fp32 [K=768][N=768] transposed -> fp16 [768 n][768 k]
// via 32x32 smem transpose, 8-byte stores.
// ---------------------------------------------------------------------------
__global__ __launch_bounds__(256) void pack_W3_kernel(
    const float* __restrict__ W0, const float* __restrict__ W1,
    const float* __restrict__ W2,
    __half* __restrict__ O0, __half* __restrict__ O1, __half* __restrict__ O2)
{
    const int z = blockIdx.z;
    const float* W = (z == 0) ? W0 : (z == 1) ? W1 : W2;
    __half* O = (z == 0) ? O0 : (z == 1) ? O1 : O2;

    __shared__ float t[32][33];
    const int tx = threadIdx.x & 31;
    const int ty = threadIdx.x >> 5;           // 0..7
    const int k0 = blockIdx.y * 32;
    const int n0 = blockIdx.x * 32;
#pragma unroll
    for (int i = 0; i < 4; i++)
        t[ty + i * 8][tx] = W[(size_t)(k0 + ty + i * 8) * D_MOD + n0 + tx];
    __syncthreads();

    const int nl = threadIdx.x >> 3;           // 0..31
    const int kg = (threadIdx.x & 7) * 4;      // 0..28
    uint2 hw = make_uint2(
        packh2(__float2half(t[kg + 0][nl]), __float2half(t[kg + 1][nl])),
        packh2(__float2half(t[kg + 2][nl]), __float2half(t[kg + 3][nl])));
    *(uint2*)&O[(size_t)(n0 + nl) * GK + k0 + kg] = hw;
}

// ---------------------------------------------------------------------------
// HMMA fp16 GEMM (batched over blockIdx.z): C = A @ W^T + bias (fp32 accum)
// CTA 128x128, 8 warps (warp tile 64x32), K-chunk 64, 3-stage cp.async.
// ---------------------------------------------------------------------------
#define GSTAGES 3
#define STAGE_BYTES 32768   // A 16KB + B 16KB

__global__ __launch_bounds__(256, 2) void gemm_mma_kernel(
    const __half* __restrict__ a0, const __half* __restrict__ a1,
    const __half* __restrict__ a2,
    const __half* __restrict__ b0, const __half* __restrict__ b1,
    const __half* __restrict__ b2,
    const float* __restrict__ bias0, const float* __restrict__ bias1,
    const float* __restrict__ bias2,
    float* __restrict__ c0, float* __restrict__ c1, float* __restrict__ c2)
{
    const int z = blockIdx.z;
    const __half* Apk = (z == 0) ? a0 : (z == 1) ? a1 : a2;
    const __half* Bpk = (z == 0) ? b0 : (z == 1) ? b1 : b2;
    const float* bias = (z == 0) ? bias0 : (z == 1) ? bias1 : bias2;
    float* C = (z == 0) ? c0 : (z == 1) ? c1 : c2;

    extern __shared__ char smem[];
    const unsigned sb = smem_u32(smem);

    const int tid  = threadIdx.x;
    const int wid  = tid >> 5;
    const int lane = tid & 31;
    const int wm   = wid & 1;
    const int wn   = wid >> 1;
    const int mBase = blockIdx.y * 128;
    const int nBase = blockIdx.x * 128;

    const __half* aSrc = Apk + (size_t)mBase * GK;
    const __half* bSrc = Bpk + (size_t)nBase * GK;

    const int lrow = tid >> 1;
    const int lch0 = (tid & 1) << 2;
    auto load_stage = [&](int stage, int chunk) {
        unsigned sA = sb + stage * STAGE_BYTES;
        unsigned sB = sA + 16384;
        const __half* ga = aSrc + (size_t)lrow * GK + chunk * CHUNK_K + lch0 * 8;
        const __half* gb = bSrc + (size_t)lrow * GK + chunk * CHUNK_K + lch0 * 8;
        unsigned rbase = lrow * 128;
        unsigned rx = lrow & 7;
#pragma unroll
        for (int c = 0; c < 4; c++) {
            unsigned swoff = rbase + (((lch0 + c) ^ rx) << 4);
            cp_async16(sA + swoff, ga + c * 8);
            cp_async16(sB + swoff, gb + c * 8);
        }
    };

    float acc[4][4][4];
#pragma unroll
    for (int i = 0; i < 4; i++)
#pragma unroll
        for (int j = 0; j < 4; j++)
#pragma unroll
            for (int r = 0; r < 4; r++) acc[i][j][r] = 0.f;

    load_stage(0, 0); cp_commit();
    load_stage(1, 1); cp_commit();

    const int arow_l = wm * 64 + (lane & 15);
    const int asel   = lane >> 4;
    const int brow_l = wn * 32 + ((lane & 16) ? 8 : 0) + (lane & 7);
    const int bsel   = (lane >> 3) & 1;

    for (int c = 0; c < NCHUNK; c++) {
        cp_wait1();
        __syncthreads();
        if (c + 2 < NCHUNK) { load_stage((c + 2) % GSTAGES, c + 2); cp_commit(); }
        else                { cp_commit(); }

        unsigned sA = sb + (c % GSTAGES) * STAGE_BYTES;
        unsigned sB = sA + 16384;

#pragma unroll
        for (int ks = 0; ks < 4; ks++) {
            unsigned afr[4][4];
#pragma unroll
            for (int i = 0; i < 4; i++) {
                int row = arow_l + i * 16;
                int ch = 2 * ks + asel;
                ldsm_x4(afr[i], sA + row * 128 + ((ch ^ (row & 7)) << 4));
            }
            unsigned bfr[2][4];
#pragma unroll
            for (int p = 0; p < 2; p++) {
                int row = brow_l + p * 16;
                int ch = 2 * ks + bsel;
                ldsm_x4(bfr[p], sB + row * 128 + ((ch ^ (row & 7)) << 4));
            }
#pragma unroll
            for (int i = 0; i < 4; i++) {
#pragma unroll
                for (int p = 0; p < 2; p++) {
                    mma16816(acc[i][2 * p],     afr[i], &bfr[p][0]);
                    mma16816(acc[i][2 * p + 1], afr[i], &bfr[p][2]);
                }
            }
        }
    }

#pragma unroll
    for (int i = 0; i < 4; i++) {
        int row = mBase + wm * 64 + i * 16 + (lane >> 2);
#pragma unroll
        for (int j = 0; j < 4; j++) {
            int col = nBase + wn * 32 + j * 8 + (lane & 3) * 2;
            float2 b2 = *(const float2*)&bias[col];
            float2 o0 = make_float2(acc[i][j][0] + b2.x, acc[i][j][1] + b2.y);
            float2 o1 = make_float2(acc[i][j][2] + b2.x, acc[i][j][3] + b2.y);
            *(float2*)&C[(size_t)row * D_MOD + col] = o0;
            *(float2*)&C[(size_t)(row + 8) * D_MOD + col] = o1;
        }
    }
}

// ---------------------------------------------------------------------------
// Sliding-window attention v3: smem squeezed to 112KB for 2 CTAs/SM.
//   region1: Qt[64 d][64] + Kt[64 d][192]; Pt[192][68] overlays region1.
//   Vs[192][64] separate. Q/K loaders remapped: 32 lanes -> 32 distinct rows
//   (conflict-free transposed stores).
// ---------------------------------------------------------------------------
#define QT_STRIDE 64
#define KT_STRIDE 192
#define VS_STRIDE 64
#define PT_STRIDE 68
#define ATTN_SMEM_FLOATS (HDIM*QT_STRIDE + HDIM*KT_STRIDE + KW*VS_STRIDE)  // 28672

__global__ __launch_bounds__(256, 2) void attn_kernel(
    const float* __restrict__ Q, const float* __restrict__ K,
    const float* __restrict__ V, float* __restrict__ ctx)
{
    extern __shared__ float sm[];
    float* Qt = sm;                              // [64 d][64]
    float* Kt = sm + HDIM * QT_STRIDE;           // [64 d][192]
    float* Pt = sm;                              // overlay [192 j][68] (13056 <= 16384)
    float* Vs = sm + HDIM * QT_STRIDE + HDIM * KT_STRIDE;   // [192 j][64]

    const int qt = blockIdx.x;
    const int h  = blockIdx.y;
    const int qbase = qt * QT;
    const int kbase = qbase - 64;
    const int col0 = h * HDIM;
    const int tid = threadIdx.x;

    // Q transposed: lanes spread over rows -> conflict-free scalar stores
#pragma unroll
    for (int it = 0; it < 4; it++) {
        int idx = it * 256 + tid;                // 0..1023
        int r = idx & 63;
        int cg = idx >> 6;                       // 0..15
        float4 q4 = *(const float4*)&Q[(size_t)(qbase + r) * D_MOD + col0 + cg * 4];
        Qt[(cg * 4 + 0) * QT_STRIDE + r] = q4.x;
        Qt[(cg * 4 + 1) * QT_STRIDE + r] = q4.y;
        Qt[(cg * 4 + 2) * QT_STRIDE + r] = q4.z;
        Qt[(cg * 4 + 3) * QT_STRIDE + r] = q4.w;
    }
    // K transposed: same row-spread mapping
#pragma unroll
    for (int it = 0; it < 12; it++) {
        int idx = it * 256 + tid;                // 0..3071
        int j = idx % 192;
        int cg = idx / 192;                      // 0..15
        int kj = kbase + j;
        float4 kv = make_float4(0.f, 0.f, 0.f, 0.f);
        if (kj >= 0 && kj < S_LEN)
            kv = *(const float4*)&K[(size_t)kj * D_MOD + col0 + cg * 4];
        Kt[(cg * 4 + 0) * KT_STRIDE + j] = kv.x;
        Kt[(cg * 4 + 1) * KT_STRIDE + j] = kv.y;
        Kt[(cg * 4 + 2) * KT_STRIDE + j] = kv.z;
        Kt[(cg * 4 + 3) * KT_STRIDE + j] = kv.w;
    }
    // V row-major: lanes spread over columns (coalesced global, 128-bit stores)
#pragma unroll
    for (int it = 0; it < 12; it++) {
        int idx = it * 256 + tid;
        int j = idx >> 4;
        int c4 = (idx & 15) << 2;
        int kj = kbase + j;
        float4 vv = make_float4(0.f, 0.f, 0.f, 0.f);
        if (kj >= 0 && kj < S_LEN)
            vv = *(const float4*)&V[(size_t)kj * D_MOD + col0 + c4];
        *(float4*)&Vs[j * VS_STRIDE + c4] = vv;
    }
    __syncthreads();

    const int tx = tid & 15;
    const int ty = tid >> 4;
    const int m0 = ty * 4;
    const int n0s = tx * 12;

    float acc[4][12];
#pragma unroll
    for (int i = 0; i < 4; i++)
#pragma unroll
        for (int t = 0; t < 12; t++) acc[i][t] = 0.f;

#pragma unroll 2
    for (int d = 0; d < HDIM; d++) {
        float4 q4 = *(const float4*)&Qt[d * QT_STRIDE + m0];
        float4 k0 = *(const float4*)&Kt[d * KT_STRIDE + n0s];
        float4 k1 = *(const float4*)&Kt[d * KT_STRIDE + n0s + 4];
        float4 k2 = *(const float4*)&Kt[d * KT_STRIDE + n0s + 8];
        float qm[4] = {q4.x, q4.y, q4.z, q4.w};
        float kn[12] = {k0.x, k0.y, k0.z, k0.w, k1.x, k1.y, k1.z, k1.w,
                        k2.x, k2.y, k2.z, k2.w};
#pragma unroll
        for (int i = 0; i < 4; i++)
#pragma unroll
            for (int t = 0; t < 12; t++)
                acc[i][t] += qm[i] * kn[t];
    }

    float mx[4], sum[4];
#pragma unroll
    for (int i = 0; i < 4; i++) {
        int r = m0 + i;
        float m = -1e30f;
#pragma unroll
        for (int t = 0; t < 12; t++) {
            int j = n0s + t;
            int kj = kbase + j;
            bool valid = (j >= r) && (j <= r + 128) && (kj >= 0) && (kj < S_LEN);
            acc[i][t] = valid ? acc[i][t] * 0.125f : -1e30f;
            m = fmaxf(m, acc[i][t]);
        }
        mx[i] = m;
    }
#pragma unroll
    for (int i = 0; i < 4; i++) {
        mx[i] = fmaxf(mx[i], __shfl_xor_sync(0xffffffffu, mx[i], 1));
        mx[i] = fmaxf(mx[i], __shfl_xor_sync(0xffffffffu, mx[i], 2));
        mx[i] = fmaxf(mx[i], __shfl_xor_sync(0xffffffffu, mx[i], 4));
        mx[i] = fmaxf(mx[i], __shfl_xor_sync(0xffffffffu, mx[i], 8));
    }
#pragma unroll
    for (int i = 0; i < 4; i++) {
        float s = 0.f;
#pragma unroll
        for (int t = 0; t < 12; t++) {
            acc[i][t] = __expf(acc[i][t] - mx[i]);
            s += acc[i][t];
        }
        sum[i] = s;
    }
#pragma unroll
    for (int i = 0; i < 4; i++) {
        sum[i] += __shfl_xor_sync(0xffffffffu, sum[i], 1);
        sum[i] += __shfl_xor_sync(0xffffffffu, sum[i], 2);
        sum[i] += __shfl_xor_sync(0xffffffffu, sum[i], 4);
        sum[i] += __shfl_xor_sync(0xffffffffu, sum[i], 8);
        sum[i] = 1.0f / sum[i];
    }

    // Pt overlays Qt/Kt: make sure everyone finished reading them.
    __syncthreads();
#pragma unroll
    for (int t = 0; t < 12; t++) {
        int j = n0s + t;
        float4 p4 = make_float4(acc[0][t] * sum[0], acc[1][t] * sum[1],
                                acc[2][t] * sum[2], acc[3][t] * sum[3]);
        *(float4*)&Pt[j * PT_STRIDE + m0] = p4;
    }
    __syncthreads();

    const int n0 = tx * 4;
    float o[4][4];
#pragma unroll
    for (int i = 0; i < 4; i++)
#pragma unroll
        for (int jj = 0; jj < 4; jj++) o[i][jj] = 0.f;

#pragma unroll 4
    for (int j = 0; j < KW; j++) {
        float4 p4 = *(const float4*)&Pt[j * PT_STRIDE + m0];
        float4 v4 = *(const float4*)&Vs[j * VS_STRIDE + n0];
        float pm[4] = {p4.x, p4.y, p4.z, p4.w};
        float vn[4] = {v4.x, v4.y, v4.z, v4.w};
#pragma unroll
        for (int i = 0; i < 4; i++)
#pragma unroll
            for (int jj = 0; jj < 4; jj++)
                o[i][jj] += pm[i] * vn[jj];
    }
#pragma unroll
    for (int i = 0; i < 4; i++) {
        float4 ov = make_float4(o[i][0], o[i][1], o[i][2], o[i][3]);
        *(float4*)&ctx[(size_t)(qbase + m0 + i) * D_MOD + col0 + n0] = ov;
    }
}

// ---------------------------------------------------------------------------
extern "C" void kernel_launch(void* const* d_in, const int* in_sizes, int n_in,
                              void* d_out, int out_size) {
    const float* query = (const float*)d_in[0];
    const float* key   = (const float*)d_in[1];
    const float* value = (const float*)d_in[2];
    const float* Wq = (const float*)d_in[3];
    const float* bq = (const float*)d_in[4];
    const float* Wk = (const float*)d_in[5];
    const float* bk = (const float*)d_in[6];
    const float* Wv = (const float*)d_in[7];
    const float* bv = (const float*)d_in[8];
    const float* Wo = (const float*)d_in[9];
    const float* bo = (const float*)d_in[10];
    float* out = (float*)d_out;

    float *qp, *kp, *vp, *cp;
    __half *apk, *bpk;
    cudaGetSymbolAddress((void**)&qp, g_Q);
    cudaGetSymbolAddress((void**)&kp, g_K);
    cudaGetSymbolAddress((void**)&vp, g_V);
    cudaGetSymbolAddress((void**)&cp, g_ctx);
    cudaGetSymbolAddress((void**)&apk, g_Apk);
    cudaGetSymbolAddress((void**)&bpk, g_Bpk);
    __half* apk0 = apk;
    __half* apk1 = apk + (size_t)S_LEN * GK;
    __half* apk2 = apk + (size_t)2 * S_LEN * GK;
    __half* bpk0 = bpk;
    __half* bpk1 = bpk + (size_t)D_MOD * GK;
    __half* bpk2 = bpk + (size_t)2 * D_MOD * GK;

    const int gemm_smem = GSTAGES * STAGE_BYTES;   // 98304
    cudaFuncSetAttribute(gemm_mma_kernel,
                         cudaFuncAttributeMaxDynamicSharedMemorySize, gemm_smem);
    const int attn_smem = ATTN_SMEM_FLOATS * sizeof(float);   // 114688
    cudaFuncSetAttribute(attn_kernel,
                         cudaFuncAttributeMaxDynamicSharedMemorySize, attn_smem);

    // ---- Fused Q/K/V projections ----
    pack_A3_kernel<<<dim3(1536, 3), 256>>>(query, key, value, apk0, apk1, apk2);
    pack_W3_kernel<<<dim3(24, 24, 3), 256>>>(Wq, Wk, Wv, bpk0, bpk1, bpk2);
    gemm_mma_kernel<<<dim3(6, 16, 3), 256, gemm_smem>>>(
        apk0, apk1, apk2, bpk0, bpk1, bpk2, bq, bk, bv, qp, kp, vp);

    // ---- Attention ----
    dim3 agrid(S_LEN / QT, N_HEADS);
    attn_kernel<<<agrid, 256, attn_smem>>>(qp, kp, vp, cp);

    // ---- Output projection ----
    pack_A3_kernel<<<dim3(1536, 1), 256>>>(cp, cp, cp, apk0, apk0, apk0);
    pack_W3_kernel<<<dim3(24, 24, 1), 256>>>(Wo, Wo, Wo, bpk0, bpk0, bpk0);
    gemm_mma_kernel<<<dim3(6, 16, 1), 256, gemm_smem>>>(
        apk0, apk0, apk0, bpk0, bpk0, bpk0, bo, bo, bo, out, out, out);
}

// round 10
// speedup vs baseline: 1.0059x; 1.0059x over previous
#include <cuda_runtime.h>
#include <cuda_fp16.h>
#include <math.h>

// ---------------- Problem constants ----------------
#define S_LEN 2048
#define D_MOD 768
#define N_HEADS 12
#define HDIM 64
#define QT 64
#define KW 192

// ---------------- fp16 GEMM constants ----------------
#define GK 768
#define NCHUNK 12          // GK / 64
#define CHUNK_K 64

// ---------------- Scratch (no cudaMalloc allowed) ----------------
__device__ float g_Q[S_LEN * D_MOD];
__device__ float g_K[S_LEN * D_MOD];
__device__ float g_V[S_LEN * D_MOD];
__device__ float g_ctx[S_LEN * D_MOD];
__device__ __align__(1024) __half g_Apk[3][S_LEN * GK];
__device__ __align__(1024) __half g_Bpk[3][D_MOD * GK];

// ---------------- PTX helpers (base sm_103-safe: sm_80 era) ----------------
__device__ __forceinline__ unsigned smem_u32(const void* p) {
    unsigned a;
    asm("{ .reg .u64 t; cvta.to.shared.u64 t, %1; cvt.u32.u64 %0, t; }"
        : "=r"(a) : "l"(p));
    return a;
}
__device__ __forceinline__ void cp_async16(unsigned saddr, const void* gptr) {
    asm volatile("cp.async.cg.shared.global [%0], [%1], 16;"
                 :: "r"(saddr), "l"(gptr));
}
__device__ __forceinline__ void cp_commit() {
    asm volatile("cp.async.commit_group;");
}
__device__ __forceinline__ void cp_wait1() {
    asm volatile("cp.async.wait_group 1;");
}
__device__ __forceinline__ void ldsm_x4(unsigned* r, unsigned addr) {
    asm volatile("ldmatrix.sync.aligned.m8n8.x4.shared.b16 {%0,%1,%2,%3}, [%4];"
                 : "=r"(r[0]), "=r"(r[1]), "=r"(r[2]), "=r"(r[3]) : "r"(addr));
}
__device__ __forceinline__ void mma16816(float* c, const unsigned* a, const unsigned* b) {
    asm volatile(
        "mma.sync.aligned.m16n8k16.row.col.f32.f16.f16.f32 "
        "{%0,%1,%2,%3}, {%4,%5,%6,%7}, {%8,%9}, {%0,%1,%2,%3};"
        : "+f"(c[0]), "+f"(c[1]), "+f"(c[2]), "+f"(c[3])
        : "r"(a[0]), "r"(a[1]), "r"(a[2]), "r"(a[3]), "r"(b[0]), "r"(b[1]));
}
__device__ __forceinline__ unsigned packh2(__half a, __half b) {
    __half2 t = __halves2half2(a, b);
    return *(unsigned*)&t;
}

// ---------------------------------------------------------------------------
// Pack A (up to 3 inputs): fp32 [2048x768] -> fp16 [2048][768]
// ---------------------------------------------------------------------------
__global__ __launch_bounds__(256) void pack_A3_kernel(
    const float* __restrict__ A0, const float* __restrict__ A1,
    const float* __restrict__ A2,
    __half* __restrict__ O0, __half* __restrict__ O1, __half* __restrict__ O2)
{
    const int z = blockIdx.y;
    const float* A = (z == 0) ? A0 : (z == 1) ? A1 : A2;
    __half* O = (z == 0) ? O0 : (z == 1) ? O1 : O2;

    int g = blockIdx.x * 256 + threadIdx.x;     // < 2048*192
    int idx4 = g * 4;
    float4 v = *(const float4*)&A[idx4];
    uint2 hw = make_uint2(packh2(__float2half(v.x), __float2half(v.y)),
                          packh2(__float2half(v.z), __float2half(v.w)));
    *(uint2*)&O[idx4] = hw;
}

// ---------------------------------------------------------------------------
// Pack W (up to 3 weights): fp32 [K=768][N=768] transposed -> fp16 [768 n][768 k]
// via 32x32 smem transpose, 8-byte stores.
// ---------------------------------------------------------------------------
__global__ __launch_bounds__(256) void pack_W3_kernel(
    const float* __restrict__ W0, const float* __restrict__ W1,
    const float* __restrict__ W2,
    __half* __restrict__ O0, __half* __restrict__ O1, __half* __restrict__ O2)
{
    const int z = blockIdx.z;
    const float* W = (z == 0) ? W0 : (z == 1) ? W1 : W2;
    __half* O = (z == 0) ? O0 : (z == 1) ? O1 : O2;

    __shared__ float t[32][33];
    const int tx = threadIdx.x & 31;
    const int ty = threadIdx.x >> 5;           // 0..7
    const int k0 = blockIdx.y * 32;
    const int n0 = blockIdx.x * 32;
#pragma unroll
    for (int i = 0; i < 4; i++)
        t[ty + i * 8][tx] = W[(size_t)(k0 + ty + i * 8) * D_MOD + n0 + tx];
    __syncthreads();

    const int nl = threadIdx.x >> 3;           // 0..31
    const int kg = (threadIdx.x & 7) * 4;      // 0..28
    uint2 hw = make_uint2(
        packh2(__float2half(t[kg + 0][nl]), __float2half(t[kg + 1][nl])),
        packh2(__float2half(t[kg + 2][nl]), __float2half(t[kg + 3][nl])));
    *(uint2*)&O[(size_t)(n0 + nl) * GK + k0 + kg] = hw;
}

// ---------------------------------------------------------------------------
// HMMA fp16 GEMM (batched over blockIdx.z): C = A @ W^T + bias (fp32 accum)
// CTA 128x128, 8 warps (warp tile 64x32), K-chunk 64, 3-stage cp.async.
// ---------------------------------------------------------------------------
#define GSTAGES 3
#define STAGE_BYTES 32768   // A 16KB + B 16KB

__global__ __launch_bounds__(256, 2) void gemm_mma_kernel(
    const __half* __restrict__ a0, const __half* __restrict__ a1,
    const __half* __restrict__ a2,
    const __half* __restrict__ b0, const __half* __restrict__ b1,
    const __half* __restrict__ b2,
    const float* __restrict__ bias0, const float* __restrict__ bias1,
    const float* __restrict__ bias2,
    float* __restrict__ c0, float* __restrict__ c1, float* __restrict__ c2)
{
    const int z = blockIdx.z;
    const __half* Apk = (z == 0) ? a0 : (z == 1) ? a1 : a2;
    const __half* Bpk = (z == 0) ? b0 : (z == 1) ? b1 : b2;
    const float* bias = (z == 0) ? bias0 : (z == 1) ? bias1 : bias2;
    float* C = (z == 0) ? c0 : (z == 1) ? c1 : c2;

    extern __shared__ char smem[];
    const unsigned sb = smem_u32(smem);

    const int tid  = threadIdx.x;
    const int wid  = tid >> 5;
    const int lane = tid & 31;
    const int wm   = wid & 1;
    const int wn   = wid >> 1;
    const int mBase = blockIdx.y * 128;
    const int nBase = blockIdx.x * 128;

    const __half* aSrc = Apk + (size_t)mBase * GK;
    const __half* bSrc = Bpk + (size_t)nBase * GK;

    const int lrow = tid >> 1;
    const int lch0 = (tid & 1) << 2;
    auto load_stage = [&](int stage, int chunk) {
        unsigned sA = sb + stage * STAGE_BYTES;
        unsigned sB = sA + 16384;
        const __half* ga = aSrc + (size_t)lrow * GK + chunk * CHUNK_K + lch0 * 8;
        const __half* gb = bSrc + (size_t)lrow * GK + chunk * CHUNK_K + lch0 * 8;
        unsigned rbase = lrow * 128;
        unsigned rx = lrow & 7;
#pragma unroll
        for (int c = 0; c < 4; c++) {
            unsigned swoff = rbase + (((lch0 + c) ^ rx) << 4);
            cp_async16(sA + swoff, ga + c * 8);
            cp_async16(sB + swoff, gb + c * 8);
        }
    };

    float acc[4][4][4];
#pragma unroll
    for (int i = 0; i < 4; i++)
#pragma unroll
        for (int j = 0; j < 4; j++)
#pragma unroll
            for (int r = 0; r < 4; r++) acc[i][j][r] = 0.f;

    load_stage(0, 0); cp_commit();
    load_stage(1, 1); cp_commit();

    const int arow_l = wm * 64 + (lane & 15);
    const int asel   = lane >> 4;
    const int brow_l = wn * 32 + ((lane & 16) ? 8 : 0) + (lane & 7);
    const int bsel   = (lane >> 3) & 1;

    for (int c = 0; c < NCHUNK; c++) {
        cp_wait1();
        __syncthreads();
        if (c + 2 < NCHUNK) { load_stage((c + 2) % GSTAGES, c + 2); cp_commit(); }
        else                { cp_commit(); }

        unsigned sA = sb + (c % GSTAGES) * STAGE_BYTES;
        unsigned sB = sA + 16384;

#pragma unroll
        for (int ks = 0; ks < 4; ks++) {
            unsigned afr[4][4];
#pragma unroll
            for (int i = 0; i < 4; i++) {
                int row = arow_l + i * 16;
                int ch = 2 * ks + asel;
                ldsm_x4(afr[i], sA + row * 128 + ((ch ^ (row & 7)) << 4));
            }
            unsigned bfr[2][4];
#pragma unroll
            for (int p = 0; p < 2; p++) {
                int row = brow_l + p * 16;
                int ch = 2 * ks + bsel;
                ldsm_x4(bfr[p], sB + row * 128 + ((ch ^ (row & 7)) << 4));
            }
#pragma unroll
            for (int i = 0; i < 4; i++) {
#pragma unroll
                for (int p = 0; p < 2; p++) {
                    mma16816(acc[i][2 * p],     afr[i], &bfr[p][0]);
                    mma16816(acc[i][2 * p + 1], afr[i], &bfr[p][2]);
                }
            }
        }
    }

#pragma unroll
    for (int i = 0; i < 4; i++) {
        int row = mBase + wm * 64 + i * 16 + (lane >> 2);
#pragma unroll
        for (int j = 0; j < 4; j++) {
            int col = nBase + wn * 32 + j * 8 + (lane & 3) * 2;
            float2 b2 = *(const float2*)&bias[col];
            float2 o0 = make_float2(acc[i][j][0] + b2.x, acc[i][j][1] + b2.y);
            float2 o1 = make_float2(acc[i][j][2] + b2.x, acc[i][j][3] + b2.y);
            *(float2*)&C[(size_t)row * D_MOD + col] = o0;
            *(float2*)&C[(size_t)(row + 8) * D_MOD + col] = o1;
        }
    }
}

// ---------------------------------------------------------------------------
// Sliding-window attention v3: smem squeezed to 112KB for 2 CTAs/SM.
//   region1: Qt[64 d][64] + Kt[64 d][192]; Pt[192][68] overlays region1.
//   Vs[192][64] separate. Q/K loaders remapped: 32 lanes -> 32 distinct rows
//   (conflict-free transposed stores).
// ---------------------------------------------------------------------------
#define QT_STRIDE 64
#define KT_STRIDE 192
#define VS_STRIDE 64
#define PT_STRIDE 68
#define ATTN_SMEM_FLOATS (HDIM*QT_STRIDE + HDIM*KT_STRIDE + KW*VS_STRIDE)  // 28672

__global__ __launch_bounds__(256, 2) void attn_kernel(
    const float* __restrict__ Q, const float* __restrict__ K,
    const float* __restrict__ V, float* __restrict__ ctx)
{
    extern __shared__ float sm[];
    float* Qt = sm;                              // [64 d][64]
    float* Kt = sm + HDIM * QT_STRIDE;           // [64 d][192]
    float* Pt = sm;                              // overlay [192 j][68] (13056 <= 16384)
    float* Vs = sm + HDIM * QT_STRIDE + HDIM * KT_STRIDE;   // [192 j][64]

    const int qt = blockIdx.x;
    const int h  = blockIdx.y;
    const int qbase = qt * QT;
    const int kbase = qbase - 64;
    const int col0 = h * HDIM;
    const int tid = threadIdx.x;

    // Q transposed: lanes spread over rows -> conflict-free scalar stores
#pragma unroll
    for (int it = 0; it < 4; it++) {
        int idx = it * 256 + tid;                // 0..1023
        int r = idx & 63;
        int cg = idx >> 6;                       // 0..15
        float4 q4 = *(const float4*)&Q[(size_t)(qbase + r) * D_MOD + col0 + cg * 4];
        Qt[(cg * 4 + 0) * QT_STRIDE + r] = q4.x;
        Qt[(cg * 4 + 1) * QT_STRIDE + r] = q4.y;
        Qt[(cg * 4 + 2) * QT_STRIDE + r] = q4.z;
        Qt[(cg * 4 + 3) * QT_STRIDE + r] = q4.w;
    }
    // K transposed: same row-spread mapping
#pragma unroll
    for (int it = 0; it < 12; it++) {
        int idx = it * 256 + tid;                // 0..3071
        int j = idx % 192;
        int cg = idx / 192;                      // 0..15
        int kj = kbase + j;
        float4 kv = make_float4(0.f, 0.f, 0.f, 0.f);
        if (kj >= 0 && kj < S_LEN)
            kv = *(const float4*)&K[(size_t)kj * D_MOD + col0 + cg * 4];
        Kt[(cg * 4 + 0) * KT_STRIDE + j] = kv.x;
        Kt[(cg * 4 + 1) * KT_STRIDE + j] = kv.y;
        Kt[(cg * 4 + 2) * KT_STRIDE + j] = kv.z;
        Kt[(cg * 4 + 3) * KT_STRIDE + j] = kv.w;
    }
    // V row-major: lanes spread over columns (coalesced global, 128-bit stores)
#pragma unroll
    for (int it = 0; it < 12; it++) {
        int idx = it * 256 + tid;
        int j = idx >> 4;
        int c4 = (idx & 15) << 2;
        int kj = kbase + j;
        float4 vv = make_float4(0.f, 0.f, 0.f, 0.f);
        if (kj >= 0 && kj < S_LEN)
            vv = *(const float4*)&V[(size_t)kj * D_MOD + col0 + c4];
        *(float4*)&Vs[j * VS_STRIDE + c4] = vv;
    }
    __syncthreads();

    const int tx = tid & 15;
    const int ty = tid >> 4;
    const int m0 = ty * 4;
    const int n0s = tx * 12;

    float acc[4][12];
#pragma unroll
    for (int i = 0; i < 4; i++)
#pragma unroll
        for (int t = 0; t < 12; t++) acc[i][t] = 0.f;

#pragma unroll 2
    for (int d = 0; d < HDIM; d++) {
        float4 q4 = *(const float4*)&Qt[d * QT_STRIDE + m0];
        float4 k0 = *(const float4*)&Kt[d * KT_STRIDE + n0s];
        float4 k1 = *(const float4*)&Kt[d * KT_STRIDE + n0s + 4];
        float4 k2 = *(const float4*)&Kt[d * KT_STRIDE + n0s + 8];
        float qm[4] = {q4.x, q4.y, q4.z, q4.w};
        float kn[12] = {k0.x, k0.y, k0.z, k0.w, k1.x, k1.y, k1.z, k1.w,
                        k2.x, k2.y, k2.z, k2.w};
#pragma unroll
        for (int i = 0; i < 4; i++)
#pragma unroll
            for (int t = 0; t < 12; t++)
                acc[i][t] += qm[i] * kn[t];
    }

    float mx[4], sum[4];
#pragma unroll
    for (int i = 0; i < 4; i++) {
        int r = m0 + i;
        float m = -1e30f;
#pragma unroll
        for (int t = 0; t < 12; t++) {
            int j = n0s + t;
            int kj = kbase + j;
            bool valid = (j >= r) && (j <= r + 128) && (kj >= 0) && (kj < S_LEN);
            acc[i][t] = valid ? acc[i][t] * 0.125f : -1e30f;
            m = fmaxf(m, acc[i][t]);
        }
        mx[i] = m;
    }
#pragma unroll
    for (int i = 0; i < 4; i++) {
        mx[i] = fmaxf(mx[i], __shfl_xor_sync(0xffffffffu, mx[i], 1));
        mx[i] = fmaxf(mx[i], __shfl_xor_sync(0xffffffffu, mx[i], 2));
        mx[i] = fmaxf(mx[i], __shfl_xor_sync(0xffffffffu, mx[i], 4));
        mx[i] = fmaxf(mx[i], __shfl_xor_sync(0xffffffffu, mx[i], 8));
    }
#pragma unroll
    for (int i = 0; i < 4; i++) {
        float s = 0.f;
#pragma unroll
        for (int t = 0; t < 12; t++) {
            acc[i][t] = __expf(acc[i][t] - mx[i]);
            s += acc[i][t];
        }
        sum[i] = s;
    }
#pragma unroll
    for (int i = 0; i < 4; i++) {
        sum[i] += __shfl_xor_sync(0xffffffffu, sum[i], 1);
        sum[i] += __shfl_xor_sync(0xffffffffu, sum[i], 2);
        sum[i] += __shfl_xor_sync(0xffffffffu, sum[i], 4);
        sum[i] += __shfl_xor_sync(0xffffffffu, sum[i], 8);
        sum[i] = 1.0f / sum[i];
    }

    // Pt overlays Qt/Kt: make sure everyone finished reading them.
    __syncthreads();
#pragma unroll
    for (int t = 0; t < 12; t++) {
        int j = n0s + t;
        float4 p4 = make_float4(acc[0][t] * sum[0], acc[1][t] * sum[1],
                                acc[2][t] * sum[2], acc[3][t] * sum[3]);
        *(float4*)&Pt[j * PT_STRIDE + m0] = p4;
    }
    __syncthreads();

    const int n0 = tx * 4;
    float o[4][4];
#pragma unroll
    for (int i = 0; i < 4; i++)
#pragma unroll
        for (int jj = 0; jj < 4; jj++) o[i][jj] = 0.f;

#pragma unroll 4
    for (int j = 0; j < KW; j++) {
        float4 p4 = *(const float4*)&Pt[j * PT_STRIDE + m0];
        float4 v4 = *(const float4*)&Vs[j * VS_STRIDE + n0];
        float pm[4] = {p4.x, p4.y, p4.z, p4.w};
        float vn[4] = {v4.x, v4.y, v4.z, v4.w};
#pragma unroll
        for (int i = 0; i < 4; i++)
#pragma unroll
            for (int jj = 0; jj < 4; jj++)
                o[i][jj] += pm[i] * vn[jj];
    }
#pragma unroll
    for (int i = 0; i < 4; i++) {
        float4 ov = make_float4(o[i][0], o[i][1], o[i][2], o[i][3]);
        *(float4*)&ctx[(size_t)(qbase + m0 + i) * D_MOD + col0 + n0] = ov;
    }
}

// ---------------------------------------------------------------------------
extern "C" void kernel_launch(void* const* d_in, const int* in_sizes, int n_in,
                              void* d_out, int out_size) {
    const float* query = (const float*)d_in[0];
    const float* key   = (const float*)d_in[1];
    const float* value = (const float*)d_in[2];
    const float* Wq = (const float*)d_in[3];
    const float* bq = (const float*)d_in[4];
    const float* Wk = (const float*)d_in[5];
    const float* bk = (const float*)d_in[6];
    const float* Wv = (const float*)d_in[7];
    const float* bv = (const float*)d_in[8];
    const float* Wo = (const float*)d_in[9];
    const float* bo = (const float*)d_in[10];
    float* out = (float*)d_out;

    float *qp, *kp, *vp, *cp;
    __half *apk, *bpk;
    cudaGetSymbolAddress((void**)&qp, g_Q);
    cudaGetSymbolAddress((void**)&kp, g_K);
    cudaGetSymbolAddress((void**)&vp, g_V);
    cudaGetSymbolAddress((void**)&cp, g_ctx);
    cudaGetSymbolAddress((void**)&apk, g_Apk);
    cudaGetSymbolAddress((void**)&bpk, g_Bpk);
    __half* apk0 = apk;
    __half* apk1 = apk + (size_t)S_LEN * GK;
    __half* apk2 = apk + (size_t)2 * S_LEN * GK;
    __half* bpk0 = bpk;
    __half* bpk1 = bpk + (size_t)D_MOD * GK;
    __half* bpk2 = bpk + (size_t)2 * D_MOD * GK;

    const int gemm_smem = GSTAGES * STAGE_BYTES;   // 98304
    cudaFuncSetAttribute(gemm_mma_kernel,
                         cudaFuncAttributeMaxDynamicSharedMemorySize, gemm_smem);
    const int attn_smem = ATTN_SMEM_FLOATS * sizeof(float);   // 114688
    cudaFuncSetAttribute(attn_kernel,
                         cudaFuncAttributeMaxDynamicSharedMemorySize, attn_smem);

    // ---- Fused Q/K/V projections ----
    pack_A3_kernel<<<dim3(1536, 3), 256>>>(query, key, value, apk0, apk1, apk2);
    pack_W3_kernel<<<dim3(24, 24, 3), 256>>>(Wq, Wk, Wv, bpk0, bpk1, bpk2);
    gemm_mma_kernel<<<dim3(6, 16, 3), 256, gemm_smem>>>(
        apk0, apk1, apk2, bpk0, bpk1, bpk2, bq, bk, bv, qp, kp, vp);

    // ---- Attention ----
    dim3 agrid(S_LEN / QT, N_HEADS);
    attn_kernel<<<agrid, 256, attn_smem>>>(qp, kp, vp, cp);

    // ---- Output projection ----
    pack_A3_kernel<<<dim3(1536, 1), 256>>>(cp, cp, cp, apk0, apk0, apk0);
    pack_W3_kernel<<<dim3(24, 24, 1), 256>>>(Wo, Wo, Wo, bpk0, bpk0, bpk0);
    gemm_mma_kernel<<<dim3(6, 16, 1), 256, gemm_smem>>>(
        apk0, apk0, apk0, bpk0, bpk0, bpk0, bo, bo, bo, out, out, out);
}

// round 11
// speedup vs baseline: 1.6604x; 1.6507x over previous
#include <cuda_runtime.h>
#include <cuda_fp16.h>
#include <math.h>

// ---------------- Problem constants ----------------
#define S_LEN 2048
#define D_MOD 768
#define N_HEADS 12
#define HDIM 64
#define QT 64
#define KW 192

// ---------------- fp16 GEMM constants ----------------
#define GK 768
#define NCHUNK 12          // GK / 64
#define CHUNK_K 64

// ---------------- Scratch (no cudaMalloc allowed) ----------------
__device__ __align__(1024) __half g_Qh[S_LEN * D_MOD];
__device__ __align__(1024) __half g_Kh[S_LEN * D_MOD];
__device__ __align__(1024) __half g_Vh[S_LEN * D_MOD];
__device__ __align__(1024) __half g_Ch[S_LEN * D_MOD];
__device__ __align__(1024) __half g_Apk[3][S_LEN * GK];
__device__ __align__(1024) __half g_Bpk[4][D_MOD * GK];

// ---------------- PTX helpers (base sm_103-safe: sm_80 era) ----------------
__device__ __forceinline__ unsigned smem_u32(const void* p) {
    unsigned a;
    asm("{ .reg .u64 t; cvta.to.shared.u64 t, %1; cvt.u32.u64 %0, t; }"
        : "=r"(a) : "l"(p));
    return a;
}
__device__ __forceinline__ void cp_async16(unsigned saddr, const void* gptr) {
    asm volatile("cp.async.cg.shared.global [%0], [%1], 16;"
                 :: "r"(saddr), "l"(gptr));
}
__device__ __forceinline__ void cp_commit() {
    asm volatile("cp.async.commit_group;");
}
__device__ __forceinline__ void cp_wait1() {
    asm volatile("cp.async.wait_group 1;");
}
__device__ __forceinline__ void cp_wait0() {
    asm volatile("cp.async.wait_group 0;");
}
__device__ __forceinline__ void ldsm_x4(unsigned* r, unsigned addr) {
    asm volatile("ldmatrix.sync.aligned.m8n8.x4.shared.b16 {%0,%1,%2,%3}, [%4];"
                 : "=r"(r[0]), "=r"(r[1]), "=r"(r[2]), "=r"(r[3]) : "r"(addr));
}
__device__ __forceinline__ void ldsm_x4_t(unsigned* r, unsigned addr) {
    asm volatile("ldmatrix.sync.aligned.m8n8.x4.trans.shared.b16 {%0,%1,%2,%3}, [%4];"
                 : "=r"(r[0]), "=r"(r[1]), "=r"(r[2]), "=r"(r[3]) : "r"(addr));
}
__device__ __forceinline__ void mma16816(float* c, const unsigned* a, const unsigned* b) {
    asm volatile(
        "mma.sync.aligned.m16n8k16.row.col.f32.f16.f16.f32 "
        "{%0,%1,%2,%3}, {%4,%5,%6,%7}, {%8,%9}, {%0,%1,%2,%3};"
        : "+f"(c[0]), "+f"(c[1]), "+f"(c[2]), "+f"(c[3])
        : "r"(a[0]), "r"(a[1]), "r"(a[2]), "r"(a[3]), "r"(b[0]), "r"(b[1]));
}
__device__ __forceinline__ unsigned packh2(__half a, __half b) {
    __half2 t = __halves2half2(a, b);
    return *(unsigned*)&t;
}
__device__ __forceinline__ unsigned packf2h2(float a, float b) {
    __half2 t = __floats2half2_rn(a, b);
    return *(unsigned*)&t;
}

// ---------------------------------------------------------------------------
// Pack A (3 inputs): fp32 [2048x768] -> fp16 [2048][768]
// ---------------------------------------------------------------------------
__global__ __launch_bounds__(256) void pack_A3_kernel(
    const float* __restrict__ A0, const float* __restrict__ A1,
    const float* __restrict__ A2,
    __half* __restrict__ O0, __half* __restrict__ O1, __half* __restrict__ O2)
{
    const int z = blockIdx.y;
    const float* A = (z == 0) ? A0 : (z == 1) ? A1 : A2;
    __half* O = (z == 0) ? O0 : (z == 1) ? O1 : O2;

    int g = blockIdx.x * 256 + threadIdx.x;
    int idx4 = g * 4;
    float4 v = *(const float4*)&A[idx4];
    uint2 hw = make_uint2(packh2(__float2half(v.x), __float2half(v.y)),
                          packh2(__float2half(v.z), __float2half(v.w)));
    *(uint2*)&O[idx4] = hw;
}

// ---------------------------------------------------------------------------
// Pack W (4 weights): fp32 [K=768][N=768] transposed -> fp16 [768 n][768 k]
// ---------------------------------------------------------------------------
__global__ __launch_bounds__(256) void pack_W4_kernel(
    const float* __restrict__ W0, const float* __restrict__ W1,
    const float* __restrict__ W2, const float* __restrict__ W3,
    __half* __restrict__ O0, __half* __restrict__ O1,
    __half* __restrict__ O2, __half* __restrict__ O3)
{
    const int z = blockIdx.z;
    const float* W = (z == 0) ? W0 : (z == 1) ? W1 : (z == 2) ? W2 : W3;
    __half* O = (z == 0) ? O0 : (z == 1) ? O1 : (z == 2) ? O2 : O3;

    __shared__ float t[32][33];
    const int tx = threadIdx.x & 31;
    const int ty = threadIdx.x >> 5;
    const int k0 = blockIdx.y * 32;
    const int n0 = blockIdx.x * 32;
#pragma unroll
    for (int i = 0; i < 4; i++)
        t[ty + i * 8][tx] = W[(size_t)(k0 + ty + i * 8) * D_MOD + n0 + tx];
    __syncthreads();

    const int nl = threadIdx.x >> 3;
    const int kg = (threadIdx.x & 7) * 4;
    uint2 hw = make_uint2(
        packh2(__float2half(t[kg + 0][nl]), __float2half(t[kg + 1][nl])),
        packh2(__float2half(t[kg + 2][nl]), __float2half(t[kg + 3][nl])));
    *(uint2*)&O[(size_t)(n0 + nl) * GK + k0 + kg] = hw;
}

// ---------------------------------------------------------------------------
// HMMA fp16 GEMM (batched over blockIdx.z): C = A @ W^T + bias (fp32 accum)
// OUT_HALF: write __half C (for q/k/v); else fp32 (final output).
// ---------------------------------------------------------------------------
#define GSTAGES 3
#define STAGE_BYTES 32768

template<bool OUT_HALF>
__global__ __launch_bounds__(256, 2) void gemm_mma_kernel(
    const __half* __restrict__ a0, const __half* __restrict__ a1,
    const __half* __restrict__ a2,
    const __half* __restrict__ b0, const __half* __restrict__ b1,
    const __half* __restrict__ b2,
    const float* __restrict__ bias0, const float* __restrict__ bias1,
    const float* __restrict__ bias2,
    float* __restrict__ cf0, float* __restrict__ cf1, float* __restrict__ cf2,
    __half* __restrict__ ch0, __half* __restrict__ ch1, __half* __restrict__ ch2)
{
    const int z = blockIdx.z;
    const __half* Apk = (z == 0) ? a0 : (z == 1) ? a1 : a2;
    const __half* Bpk = (z == 0) ? b0 : (z == 1) ? b1 : b2;
    const float* bias = (z == 0) ? bias0 : (z == 1) ? bias1 : bias2;
    float* Cf = (z == 0) ? cf0 : (z == 1) ? cf1 : cf2;
    __half* Ch = (z == 0) ? ch0 : (z == 1) ? ch1 : ch2;

    extern __shared__ char smem[];
    const unsigned sb = smem_u32(smem);

    const int tid  = threadIdx.x;
    const int wid  = tid >> 5;
    const int lane = tid & 31;
    const int wm   = wid & 1;
    const int wn   = wid >> 1;
    const int mBase = blockIdx.y * 128;
    const int nBase = blockIdx.x * 128;

    const __half* aSrc = Apk + (size_t)mBase * GK;
    const __half* bSrc = Bpk + (size_t)nBase * GK;

    const int lrow = tid >> 1;
    const int lch0 = (tid & 1) << 2;
    auto load_stage = [&](int stage, int chunk) {
        unsigned sA = sb + stage * STAGE_BYTES;
        unsigned sB = sA + 16384;
        const __half* ga = aSrc + (size_t)lrow * GK + chunk * CHUNK_K + lch0 * 8;
        const __half* gb = bSrc + (size_t)lrow * GK + chunk * CHUNK_K + lch0 * 8;
        unsigned rbase = lrow * 128;
        unsigned rx = lrow & 7;
#pragma unroll
        for (int c = 0; c < 4; c++) {
            unsigned swoff = rbase + (((lch0 + c) ^ rx) << 4);
            cp_async16(sA + swoff, ga + c * 8);
            cp_async16(sB + swoff, gb + c * 8);
        }
    };

    float acc[4][4][4];
#pragma unroll
    for (int i = 0; i < 4; i++)
#pragma unroll
        for (int j = 0; j < 4; j++)
#pragma unroll
            for (int r = 0; r < 4; r++) acc[i][j][r] = 0.f;

    load_stage(0, 0); cp_commit();
    load_stage(1, 1); cp_commit();

    const int arow_l = wm * 64 + (lane & 15);
    const int asel   = lane >> 4;
    const int brow_l = wn * 32 + ((lane & 16) ? 8 : 0) + (lane & 7);
    const int bsel   = (lane >> 3) & 1;

    for (int c = 0; c < NCHUNK; c++) {
        cp_wait1();
        __syncthreads();
        if (c + 2 < NCHUNK) { load_stage((c + 2) % GSTAGES, c + 2); cp_commit(); }
        else                { cp_commit(); }

        unsigned sA = sb + (c % GSTAGES) * STAGE_BYTES;
        unsigned sB = sA + 16384;

#pragma unroll
        for (int ks = 0; ks < 4; ks++) {
            unsigned afr[4][4];
#pragma unroll
            for (int i = 0; i < 4; i++) {
                int row = arow_l + i * 16;
                int ch = 2 * ks + asel;
                ldsm_x4(afr[i], sA + row * 128 + ((ch ^ (row & 7)) << 4));
            }
            unsigned bfr[2][4];
#pragma unroll
            for (int p = 0; p < 2; p++) {
                int row = brow_l + p * 16;
                int ch = 2 * ks + bsel;
                ldsm_x4(bfr[p], sB + row * 128 + ((ch ^ (row & 7)) << 4));
            }
#pragma unroll
            for (int i = 0; i < 4; i++) {
#pragma unroll
                for (int p = 0; p < 2; p++) {
                    mma16816(acc[i][2 * p],     afr[i], &bfr[p][0]);
                    mma16816(acc[i][2 * p + 1], afr[i], &bfr[p][2]);
                }
            }
        }
    }

#pragma unroll
    for (int i = 0; i < 4; i++) {
        int row = mBase + wm * 64 + i * 16 + (lane >> 2);
#pragma unroll
        for (int j = 0; j < 4; j++) {
            int col = nBase + wn * 32 + j * 8 + (lane & 3) * 2;
            float2 b2 = *(const float2*)&bias[col];
            if (OUT_HALF) {
                *(__half2*)&Ch[(size_t)row * D_MOD + col] =
                    __floats2half2_rn(acc[i][j][0] + b2.x, acc[i][j][1] + b2.y);
                *(__half2*)&Ch[(size_t)(row + 8) * D_MOD + col] =
                    __floats2half2_rn(acc[i][j][2] + b2.x, acc[i][j][3] + b2.y);
            } else {
                float2 o0 = make_float2(acc[i][j][0] + b2.x, acc[i][j][1] + b2.y);
                float2 o1 = make_float2(acc[i][j][2] + b2.x, acc[i][j][3] + b2.y);
                *(float2*)&Cf[(size_t)row * D_MOD + col] = o0;
                *(float2*)&Cf[(size_t)(row + 8) * D_MOD + col] = o1;
            }
        }
    }
}

// ---------------------------------------------------------------------------
// HMMA sliding-window attention.
// CTA = (qtile of 64, head), 4 warps. Warp w owns rows w*16..w*16+15 of the
// 64x192 score matrix -> softmax is warp-local. S fragments are reused as
// P fragments (FA2 register trick). V via ldmatrix.x4.trans. fp16 in/out.
// ---------------------------------------------------------------------------
#define ATTN_SMEM (8192 + 24576 + 24576)   // Q + K + V fp16 swizzled

__global__ __launch_bounds__(128) void attn_kernel(
    const __half* __restrict__ Qh, const __half* __restrict__ Kh,
    const __half* __restrict__ Vh, __half* __restrict__ Ch)
{
    extern __shared__ char smraw[];
    const unsigned sb = smem_u32(smraw);
    const unsigned sQ = sb;
    const unsigned sK = sb + 8192;
    const unsigned sV = sb + 8192 + 24576;

    const int qt = blockIdx.x;
    const int h  = blockIdx.y;
    const int qbase = qt * QT;
    const int kbase = qbase - 64;
    const int col0 = h * HDIM;
    const int tid = threadIdx.x;
    const int lane = tid & 31;
    const int w = tid >> 5;

    // ---- load Q/K/V fp16 into swizzled smem (rows of 128B = 8 chunks) ----
#pragma unroll
    for (int it = 0; it < 4; it++) {
        int idx = it * 128 + tid;          // 512 chunks
        int r = idx >> 3, c = idx & 7;
        cp_async16(sQ + r * 128 + ((c ^ (r & 7)) << 4),
                   Qh + (size_t)(qbase + r) * D_MOD + col0 + c * 8);
    }
#pragma unroll
    for (int it = 0; it < 12; it++) {
        int idx = it * 128 + tid;          // 1536 chunks
        int j = idx >> 3, c = idx & 7;
        int kj = min(max(kbase + j, 0), S_LEN - 1);   // clamp: finite garbage, masked
        cp_async16(sK + j * 128 + ((c ^ (j & 7)) << 4),
                   Kh + (size_t)kj * D_MOD + col0 + c * 8);
    }
#pragma unroll
    for (int it = 0; it < 12; it++) {
        int idx = it * 128 + tid;
        int j = idx >> 3, c = idx & 7;
        int kj = min(max(kbase + j, 0), S_LEN - 1);
        cp_async16(sV + j * 128 + ((c ^ (j & 7)) << 4),
                   Vh + (size_t)kj * D_MOD + col0 + c * 8);
    }
    cp_commit();
    cp_wait0();
    __syncthreads();

    // ---- S = Q @ K^T : warp w -> rows m0..m0+15, all 192 cols ----
    const int m0 = w * 16;
    float st[24][4];
#pragma unroll
    for (int t = 0; t < 24; t++)
#pragma unroll
        for (int r = 0; r < 4; r++) st[t][r] = 0.f;

#pragma unroll
    for (int s = 0; s < 4; s++) {
        unsigned afr[4];
        {
            int row = m0 + (lane & 15);
            int ch = 2 * s + (lane >> 4);
            ldsm_x4(afr, sQ + row * 128 + ((ch ^ (row & 7)) << 4));
        }
#pragma unroll
        for (int nt = 0; nt < 12; nt++) {
            unsigned bfr[4];
            int row = nt * 16 + ((lane & 16) ? 8 : 0) + (lane & 7);
            int ch = 2 * s + ((lane >> 3) & 1);
            ldsm_x4(bfr, sK + row * 128 + ((ch ^ (row & 7)) << 4));
            mma16816(st[2 * nt],     afr, &bfr[0]);
            mma16816(st[2 * nt + 1], afr, &bfr[2]);
        }
    }

    // ---- mask + softmax (rows r0 = m0+lane/4, r1 = r0+8; warp-local) ----
    const int r0 = m0 + (lane >> 2);
    const int r1 = r0 + 8;
    const int cj = (lane & 3) * 2;

    float mx0 = -1e30f, mx1 = -1e30f;
#pragma unroll
    for (int t = 0; t < 24; t++) {
        int j0 = 8 * t + cj, j1 = j0 + 1;
        bool in0 = ((unsigned)(kbase + j0) < (unsigned)S_LEN);
        bool in1 = ((unsigned)(kbase + j1) < (unsigned)S_LEN);
        st[t][0] = (in0 && (unsigned)(j0 - r0) <= 128u) ? st[t][0] * 0.125f : -1e30f;
        st[t][1] = (in1 && (unsigned)(j1 - r0) <= 128u) ? st[t][1] * 0.125f : -1e30f;
        st[t][2] = (in0 && (unsigned)(j0 - r1) <= 128u) ? st[t][2] * 0.125f : -1e30f;
        st[t][3] = (in1 && (unsigned)(j1 - r1) <= 128u) ? st[t][3] * 0.125f : -1e30f;
        mx0 = fmaxf(mx0, fmaxf(st[t][0], st[t][1]));
        mx1 = fmaxf(mx1, fmaxf(st[t][2], st[t][3]));
    }
    mx0 = fmaxf(mx0, __shfl_xor_sync(0xffffffffu, mx0, 1));
    mx0 = fmaxf(mx0, __shfl_xor_sync(0xffffffffu, mx0, 2));
    mx1 = fmaxf(mx1, __shfl_xor_sync(0xffffffffu, mx1, 1));
    mx1 = fmaxf(mx1, __shfl_xor_sync(0xffffffffu, mx1, 2));

    float l0 = 0.f, l1 = 0.f;
#pragma unroll
    for (int t = 0; t < 24; t++) {
        st[t][0] = __expf(st[t][0] - mx0);
        st[t][1] = __expf(st[t][1] - mx0);
        st[t][2] = __expf(st[t][2] - mx1);
        st[t][3] = __expf(st[t][3] - mx1);
        l0 += st[t][0] + st[t][1];
        l1 += st[t][2] + st[t][3];
    }
    l0 += __shfl_xor_sync(0xffffffffu, l0, 1);
    l0 += __shfl_xor_sync(0xffffffffu, l0, 2);
    l1 += __shfl_xor_sync(0xffffffffu, l1, 1);
    l1 += __shfl_xor_sync(0xffffffffu, l1, 2);
    const float inv0 = 1.0f / l0, inv1 = 1.0f / l1;
#pragma unroll
    for (int t = 0; t < 24; t++) {
        st[t][0] *= inv0; st[t][1] *= inv0;
        st[t][2] *= inv1; st[t][3] *= inv1;
    }

    // ---- ctx = P @ V : A-frags from st regs, B via ldmatrix.trans ----
    float o[8][4];
#pragma unroll
    for (int g = 0; g < 8; g++)
#pragma unroll
        for (int r = 0; r < 4; r++) o[g][r] = 0.f;

#pragma unroll
    for (int kk = 0; kk < 12; kk++) {
        unsigned a[4];
        a[0] = packf2h2(st[2 * kk][0],     st[2 * kk][1]);
        a[1] = packf2h2(st[2 * kk][2],     st[2 * kk][3]);
        a[2] = packf2h2(st[2 * kk + 1][0], st[2 * kk + 1][1]);
        a[3] = packf2h2(st[2 * kk + 1][2], st[2 * kk + 1][3]);
        int row = kk * 16 + (lane & 15);
#pragma unroll
        for (int g = 0; g < 4; g++) {
            unsigned bfr[4];
            int ch = 2 * g + (lane >> 4);
            ldsm_x4_t(bfr, sV + row * 128 + ((ch ^ (row & 7)) << 4));
            mma16816(o[2 * g],     a, &bfr[0]);
            mma16816(o[2 * g + 1], a, &bfr[2]);
        }
    }

    // ---- store ctx fp16 ----
#pragma unroll
    for (int g = 0; g < 8; g++) {
        int d = col0 + 8 * g + cj;
        *(__half2*)&Ch[(size_t)(qbase + r0) * D_MOD + d] =
            __floats2half2_rn(o[g][0], o[g][1]);
        *(__half2*)&Ch[(size_t)(qbase + r1) * D_MOD + d] =
            __floats2half2_rn(o[g][2], o[g][3]);
    }
}

// ---------------------------------------------------------------------------
extern "C" void kernel_launch(void* const* d_in, const int* in_sizes, int n_in,
                              void* d_out, int out_size) {
    const float* query = (const float*)d_in[0];
    const float* key   = (const float*)d_in[1];
    const float* value = (const float*)d_in[2];
    const float* Wq = (const float*)d_in[3];
    const float* bq = (const float*)d_in[4];
    const float* Wk = (const float*)d_in[5];
    const float* bk = (const float*)d_in[6];
    const float* Wv = (const float*)d_in[7];
    const float* bv = (const float*)d_in[8];
    const float* Wo = (const float*)d_in[9];
    const float* bo = (const float*)d_in[10];
    float* out = (float*)d_out;

    __half *qh, *kh, *vh, *ch, *apk, *bpk;
    cudaGetSymbolAddress((void**)&qh, g_Qh);
    cudaGetSymbolAddress((void**)&kh, g_Kh);
    cudaGetSymbolAddress((void**)&vh, g_Vh);
    cudaGetSymbolAddress((void**)&ch, g_Ch);
    cudaGetSymbolAddress((void**)&apk, g_Apk);
    cudaGetSymbolAddress((void**)&bpk, g_Bpk);
    __half* apk0 = apk;
    __half* apk1 = apk + (size_t)S_LEN * GK;
    __half* apk2 = apk + (size_t)2 * S_LEN * GK;
    __half* bpk0 = bpk;
    __half* bpk1 = bpk + (size_t)D_MOD * GK;
    __half* bpk2 = bpk + (size_t)2 * D_MOD * GK;
    __half* bpk3 = bpk + (size_t)3 * D_MOD * GK;

    const int gemm_smem = GSTAGES * STAGE_BYTES;   // 98304
    cudaFuncSetAttribute(gemm_mma_kernel<true>,
                         cudaFuncAttributeMaxDynamicSharedMemorySize, gemm_smem);
    cudaFuncSetAttribute(gemm_mma_kernel<false>,
                         cudaFuncAttributeMaxDynamicSharedMemorySize, gemm_smem);
    cudaFuncSetAttribute(attn_kernel,
                         cudaFuncAttributeMaxDynamicSharedMemorySize, ATTN_SMEM);

    // ---- packs ----
    pack_A3_kernel<<<dim3(1536, 3), 256>>>(query, key, value, apk0, apk1, apk2);
    pack_W4_kernel<<<dim3(24, 24, 4), 256>>>(Wq, Wk, Wv, Wo,
                                             bpk0, bpk1, bpk2, bpk3);

    // ---- fused Q/K/V projections (fp16 out) ----
    gemm_mma_kernel<true><<<dim3(6, 16, 3), 256, gemm_smem>>>(
        apk0, apk1, apk2, bpk0, bpk1, bpk2, bq, bk, bv,
        (float*)nullptr, (float*)nullptr, (float*)nullptr, qh, kh, vh);

    // ---- attention (fp16 in/out, HMMA) ----
    attn_kernel<<<dim3(S_LEN / QT, N_HEADS), 128, ATTN_SMEM>>>(qh, kh, vh, ch);

    // ---- output projection (fp32 out) ----
    gemm_mma_kernel<false><<<dim3(6, 16, 1), 256, gemm_smem>>>(
        ch, ch, ch, bpk3, bpk3, bpk3, bo, bo, bo,
        out, out, out, (__half*)nullptr, (__half*)nullptr, (__half*)nullptr);
}

// round 13
// speedup vs baseline: 2.1207x; 1.2772x over previous
#include <cuda_runtime.h>
#include <cuda_fp16.h>
#include <math.h>

// ---------------- Problem constants ----------------
#define S_LEN 2048
#define D_MOD 768
#define N_HEADS 12
#define HDIM 64
#define QT 64
#define KW 192

// ---------------- fp16 GEMM constants ----------------
#define GK 768
#define NCHUNK 12          // GK / 64
#define CHUNK_K 64

// ---------------- Scratch (no cudaMalloc allowed) ----------------
__device__ __align__(1024) __half g_Qh[S_LEN * D_MOD];
__device__ __align__(1024) __half g_Kh[S_LEN * D_MOD];
__device__ __align__(1024) __half g_Vh[S_LEN * D_MOD];
__device__ __align__(1024) __half g_Ch[S_LEN * D_MOD];
__device__ __align__(1024) __half g_Ah[3][S_LEN * D_MOD];   // fp16 activations
__device__ __align__(1024) __half g_Wh[4][D_MOD * D_MOD];   // fp16 weights [k][n]

// ---------------- PTX helpers (base sm_103-safe: sm_80 era) ----------------
__device__ __forceinline__ unsigned smem_u32(const void* p) {
    unsigned a;
    asm("{ .reg .u64 t; cvta.to.shared.u64 t, %1; cvt.u32.u64 %0, t; }"
        : "=r"(a) : "l"(p));
    return a;
}
__device__ __forceinline__ void cp_async16(unsigned saddr, const void* gptr) {
    asm volatile("cp.async.cg.shared.global [%0], [%1], 16;"
                 :: "r"(saddr), "l"(gptr));
}
__device__ __forceinline__ void cp_commit() {
    asm volatile("cp.async.commit_group;");
}
__device__ __forceinline__ void cp_wait1() {
    asm volatile("cp.async.wait_group 1;");
}
__device__ __forceinline__ void cp_wait0() {
    asm volatile("cp.async.wait_group 0;");
}
__device__ __forceinline__ void ldsm_x4(unsigned* r, unsigned addr) {
    asm volatile("ldmatrix.sync.aligned.m8n8.x4.shared.b16 {%0,%1,%2,%3}, [%4];"
                 : "=r"(r[0]), "=r"(r[1]), "=r"(r[2]), "=r"(r[3]) : "r"(addr));
}
__device__ __forceinline__ void ldsm_x4_t(unsigned* r, unsigned addr) {
    asm volatile("ldmatrix.sync.aligned.m8n8.x4.trans.shared.b16 {%0,%1,%2,%3}, [%4];"
                 : "=r"(r[0]), "=r"(r[1]), "=r"(r[2]), "=r"(r[3]) : "r"(addr));
}
__device__ __forceinline__ void mma16816(float* c, const unsigned* a, const unsigned* b) {
    asm volatile(
        "mma.sync.aligned.m16n8k16.row.col.f32.f16.f16.f32 "
        "{%0,%1,%2,%3}, {%4,%5,%6,%7}, {%8,%9}, {%0,%1,%2,%3};"
        : "+f"(c[0]), "+f"(c[1]), "+f"(c[2]), "+f"(c[3])
        : "r"(a[0]), "r"(a[1]), "r"(a[2]), "r"(a[3]), "r"(b[0]), "r"(b[1]));
}
__device__ __forceinline__ unsigned packh2(__half a, __half b) {
    __half2 t = __halves2half2(a, b);
    return *(unsigned*)&t;
}
__device__ __forceinline__ unsigned packf2h2(float a, float b) {
    __half2 t = __floats2half2_rn(a, b);
    return *(unsigned*)&t;
}

// ---------------------------------------------------------------------------
// Fused pack: pure fp32 -> fp16 identity convert for 7 arrays.
// z 0..2: activations (2048x768 = 393216 float4);  z 3..6: weights [k][n]
// (768x768 = 147456 float4). No transpose anywhere.
// ---------------------------------------------------------------------------
__global__ __launch_bounds__(256) void pack_all_kernel(
    const float* __restrict__ A0, const float* __restrict__ A1,
    const float* __restrict__ A2,
    const float* __restrict__ W0, const float* __restrict__ W1,
    const float* __restrict__ W2, const float* __restrict__ W3,
    __half* __restrict__ OA0, __half* __restrict__ OA1, __half* __restrict__ OA2,
    __half* __restrict__ OW0, __half* __restrict__ OW1,
    __half* __restrict__ OW2, __half* __restrict__ OW3)
{
    const int z = blockIdx.y;
    const float* src;
    __half* dst;
    int n4;
    switch (z) {
        case 0: src = A0; dst = OA0; n4 = 393216; break;
        case 1: src = A1; dst = OA1; n4 = 393216; break;
        case 2: src = A2; dst = OA2; n4 = 393216; break;
        case 3: src = W0; dst = OW0; n4 = 147456; break;
        case 4: src = W1; dst = OW1; n4 = 147456; break;
        case 5: src = W2; dst = OW2; n4 = 147456; break;
        default: src = W3; dst = OW3; n4 = 147456; break;
    }
    int g = blockIdx.x * 256 + threadIdx.x;
    if (g >= n4) return;
    float4 v = *(const float4*)&src[g * 4];
    uint2 hw = make_uint2(packh2(__float2half(v.x), __float2half(v.y)),
                          packh2(__float2half(v.z), __float2half(v.w)));
    *(uint2*)&dst[g * 4] = hw;
}

// ---------------------------------------------------------------------------
// HMMA fp16 GEMM, templated on NG (16-wide n-groups per warp):
//   NG=2 -> CTA 128x128;  NG=1 -> CTA 128x64 (for SM-coverage on small grids)
// A row-major [m][k]; W row-major [k][n], B-fragments via ldmatrix.trans.
// fp32 accum; OUT_HALF selects fp16 vs fp32 C.
// ---------------------------------------------------------------------------
#define GSTAGES 3

template<int NG, bool OUT_HALF>
__global__ __launch_bounds__(256, 2) void gemm_mma_kernel(
    const __half* __restrict__ a0, const __half* __restrict__ a1,
    const __half* __restrict__ a2,
    const __half* __restrict__ b0, const __half* __restrict__ b1,
    const __half* __restrict__ b2,
    const float* __restrict__ bias0, const float* __restrict__ bias1,
    const float* __restrict__ bias2,
    float* __restrict__ cf0, float* __restrict__ cf1, float* __restrict__ cf2,
    __half* __restrict__ ch0, __half* __restrict__ ch1, __half* __restrict__ ch2)
{
    constexpr int N_TILE = 64 * NG;
    constexpr int B_ROWB = 128 * NG;            // bytes per B smem row
    constexpr int A_BYTES = 16384;              // 128 rows x 128B
    constexpr int B_BYTES = 64 * B_ROWB;        // 64 k-rows
    constexpr int STG_B = A_BYTES + B_BYTES;

    const int z = blockIdx.z;
    const __half* Ah = (z == 0) ? a0 : (z == 1) ? a1 : a2;
    const __half* Wh = (z == 0) ? b0 : (z == 1) ? b1 : b2;
    const float* bias = (z == 0) ? bias0 : (z == 1) ? bias1 : bias2;
    float* Cf = (z == 0) ? cf0 : (z == 1) ? cf1 : cf2;
    __half* Ch = (z == 0) ? ch0 : (z == 1) ? ch1 : ch2;

    extern __shared__ char smem[];
    const unsigned sb = smem_u32(smem);

    const int tid  = threadIdx.x;
    const int wid  = tid >> 5;
    const int lane = tid & 31;
    const int wm   = wid & 1;                   // 2 warp rows x 64
    const int wn   = wid >> 1;                  // 4 warp cols x 16*NG
    const int mBase = blockIdx.y * 128;
    const int nBase = blockIdx.x * N_TILE;

    const __half* aSrc = Ah + (size_t)mBase * GK;

    // A: 1024 chunks (128 rows x 8);  B: 64 rows x 2*NG*8 chunks
    auto load_stage = [&](int stage, int chunk) {
        unsigned sA = sb + stage * STG_B;
        unsigned sB = sA + A_BYTES;
        // A tile
#pragma unroll
        for (int it = 0; it < 4; it++) {
            int idx = it * 256 + tid;
            int r = idx >> 3, c = idx & 7;
            cp_async16(sA + r * 128 + ((c ^ (r & 7)) << 4),
                       aSrc + (size_t)r * GK + chunk * CHUNK_K + c * 8);
        }
        // B tile: W[k0:k0+64][nBase:nBase+N_TILE]
        const __half* bSrc = Wh + (size_t)chunk * CHUNK_K * D_MOD + nBase;
#pragma unroll
        for (int it = 0; it < 2 * NG; it++) {
            int idx = it * 256 + tid;
            int r = idx >> (3 + NG / 2);        // NG=2: idx>>4 ; NG=1: idx>>3
            int c16 = idx & (8 * NG - 1);       // chunk-of-16B within row
            unsigned off = r * B_ROWB + ((c16 >> 3) << 7)
                         + (((c16 & 7) ^ (r & 7)) << 4);
            cp_async16(sB + off, bSrc + (size_t)r * D_MOD + c16 * 8);
        }
    };

    float acc[4][2 * NG][4];
#pragma unroll
    for (int i = 0; i < 4; i++)
#pragma unroll
        for (int j = 0; j < 2 * NG; j++)
#pragma unroll
            for (int r = 0; r < 4; r++) acc[i][j][r] = 0.f;

    load_stage(0, 0); cp_commit();
    load_stage(1, 1); cp_commit();

    const int arow_l = wm * 64 + (lane & 15);
    const int asel   = lane >> 4;
    const int brow_l = lane & 15;               // k-row within 16
    const int bsel   = lane >> 4;

    for (int c = 0; c < NCHUNK; c++) {
        cp_wait1();
        __syncthreads();
        if (c + 2 < NCHUNK) { load_stage((c + 2) % GSTAGES, c + 2); cp_commit(); }
        else                { cp_commit(); }

        unsigned sA = sb + (c % GSTAGES) * STG_B;
        unsigned sB = sA + A_BYTES;

#pragma unroll
        for (int ks = 0; ks < 4; ks++) {
            // B fragments first (trans-ldsm from row-major [k][n])
            unsigned bfr[NG][4];
#pragma unroll
            for (int g = 0; g < NG; g++) {
                int row = ks * 16 + brow_l;
                int cn = wn * 2 * NG + 2 * g + bsel;
                ldsm_x4_t(bfr[g], sB + row * B_ROWB + ((cn >> 3) << 7)
                                   + (((cn & 7) ^ (row & 7)) << 4));
            }
            unsigned afr[4][4];
#pragma unroll
            for (int i = 0; i < 4; i++) {
                int row = arow_l + i * 16;
                int ch = 2 * ks + asel;
                ldsm_x4(afr[i], sA + row * 128 + ((ch ^ (row & 7)) << 4));
            }
#pragma unroll
            for (int i = 0; i < 4; i++) {
#pragma unroll
                for (int g = 0; g < NG; g++) {
                    mma16816(acc[i][2 * g],     afr[i], &bfr[g][0]);
                    mma16816(acc[i][2 * g + 1], afr[i], &bfr[g][2]);
                }
            }
        }
    }

#pragma unroll
    for (int i = 0; i < 4; i++) {
        int row = mBase + wm * 64 + i * 16 + (lane >> 2);
#pragma unroll
        for (int j = 0; j < 2 * NG; j++) {
            int col = nBase + wn * 16 * NG + j * 8 + (lane & 3) * 2;
            float2 b2 = *(const float2*)&bias[col];
            if (OUT_HALF) {
                *(__half2*)&Ch[(size_t)row * D_MOD + col] =
                    __floats2half2_rn(acc[i][j][0] + b2.x, acc[i][j][1] + b2.y);
                *(__half2*)&Ch[(size_t)(row + 8) * D_MOD + col] =
                    __floats2half2_rn(acc[i][j][2] + b2.x, acc[i][j][3] + b2.y);
            } else {
                float2 o0 = make_float2(acc[i][j][0] + b2.x, acc[i][j][1] + b2.y);
                float2 o1 = make_float2(acc[i][j][2] + b2.x, acc[i][j][3] + b2.y);
                *(float2*)&Cf[(size_t)row * D_MOD + col] = o0;
                *(float2*)&Cf[(size_t)(row + 8) * D_MOD + col] = o1;
            }
        }
    }
}

// ---------------------------------------------------------------------------
// HMMA sliding-window attention (unchanged from round 11: ~11us)
// ---------------------------------------------------------------------------
#define ATTN_SMEM (8192 + 24576 + 24576)

__global__ __launch_bounds__(128) void attn_kernel(
    const __half* __restrict__ Qh, const __half* __restrict__ Kh,
    const __half* __restrict__ Vh, __half* __restrict__ Ch)
{
    extern __shared__ char smraw[];
    const unsigned sb = smem_u32(smraw);
    const unsigned sQ = sb;
    const unsigned sK = sb + 8192;
    const unsigned sV = sb + 8192 + 24576;

    const int qt = blockIdx.x;
    const int h  = blockIdx.y;
    const int qbase = qt * QT;
    const int kbase = qbase - 64;
    const int col0 = h * HDIM;
    const int tid = threadIdx.x;
    const int lane = tid & 31;
    const int w = tid >> 5;

#pragma unroll
    for (int it = 0; it < 4; it++) {
        int idx = it * 128 + tid;
        int r = idx >> 3, c = idx & 7;
        cp_async16(sQ + r * 128 + ((c ^ (r & 7)) << 4),
                   Qh + (size_t)(qbase + r) * D_MOD + col0 + c * 8);
    }
#pragma unroll
    for (int it = 0; it < 12; it++) {
        int idx = it * 128 + tid;
        int j = idx >> 3, c = idx & 7;
        int kj = min(max(kbase + j, 0), S_LEN - 1);
        cp_async16(sK + j * 128 + ((c ^ (j & 7)) << 4),
                   Kh + (size_t)kj * D_MOD + col0 + c * 8);
    }
#pragma unroll
    for (int it = 0; it < 12; it++) {
        int idx = it * 128 + tid;
        int j = idx >> 3, c = idx & 7;
        int kj = min(max(kbase + j, 0), S_LEN - 1);
        cp_async16(sV + j * 128 + ((c ^ (j & 7)) << 4),
                   Vh + (size_t)kj * D_MOD + col0 + c * 8);
    }
    cp_commit();
    cp_wait0();
    __syncthreads();

    const int m0 = w * 16;
    float st[24][4];
#pragma unroll
    for (int t = 0; t < 24; t++)
#pragma unroll
        for (int r = 0; r < 4; r++) st[t][r] = 0.f;

#pragma unroll
    for (int s = 0; s < 4; s++) {
        unsigned afr[4];
        {
            int row = m0 + (lane & 15);
            int ch = 2 * s + (lane >> 4);
            ldsm_x4(afr, sQ + row * 128 + ((ch ^ (row & 7)) << 4));
        }
#pragma unroll
        for (int nt = 0; nt < 12; nt++) {
            unsigned bfr[4];
            int row = nt * 16 + ((lane & 16) ? 8 : 0) + (lane & 7);
            int ch = 2 * s + ((lane >> 3) & 1);
            ldsm_x4(bfr, sK + row * 128 + ((ch ^ (row & 7)) << 4));
            mma16816(st[2 * nt],     afr, &bfr[0]);
            mma16816(st[2 * nt + 1], afr, &bfr[2]);
        }
    }

    const int r0 = m0 + (lane >> 2);
    const int r1 = r0 + 8;
    const int cj = (lane & 3) * 2;

    float mx0 = -1e30f, mx1 = -1e30f;
#pragma unroll
    for (int t = 0; t < 24; t++) {
        int j0 = 8 * t + cj, j1 = j0 + 1;
        bool in0 = ((unsigned)(kbase + j0) < (unsigned)S_LEN);
        bool in1 = ((unsigned)(kbase + j1) < (unsigned)S_LEN);
        st[t][0] = (in0 && (unsigned)(j0 - r0) <= 128u) ? st[t][0] * 0.125f : -1e30f;
        st[t][1] = (in1 && (unsigned)(j1 - r0) <= 128u) ? st[t][1] * 0.125f : -1e30f;
        st[t][2] = (in0 && (unsigned)(j0 - r1) <= 128u) ? st[t][2] * 0.125f : -1e30f;
        st[t][3] = (in1 && (unsigned)(j1 - r1) <= 128u) ? st[t][3] * 0.125f : -1e30f;
        mx0 = fmaxf(mx0, fmaxf(st[t][0], st[t][1]));
        mx1 = fmaxf(mx1, fmaxf(st[t][2], st[t][3]));
    }
    mx0 = fmaxf(mx0, __shfl_xor_sync(0xffffffffu, mx0, 1));
    mx0 = fmaxf(mx0, __shfl_xor_sync(0xffffffffu, mx0, 2));
    mx1 = fmaxf(mx1, __shfl_xor_sync(0xffffffffu, mx1, 1));
    mx1 = fmaxf(mx1, __shfl_xor_sync(0xffffffffu, mx1, 2));

    float l0 = 0.f, l1 = 0.f;
#pragma unroll
    for (int t = 0; t < 24; t++) {
        st[t][0] = __expf(st[t][0] - mx0);
        st[t][1] = __expf(st[t][1] - mx0);
        st[t][2] = __expf(st[t][2] - mx1);
        st[t][3] = __expf(st[t][3] - mx1);
        l0 += st[t][0] + st[t][1];
        l1 += st[t][2] + st[t][3];
    }
    l0 += __shfl_xor_sync(0xffffffffu, l0, 1);
    l0 += __shfl_xor_sync(0xffffffffu, l0, 2);
    l1 += __shfl_xor_sync(0xffffffffu, l1, 1);
    l1 += __shfl_xor_sync(0xffffffffu, l1, 2);
    const float inv0 = 1.0f / l0, inv1 = 1.0f / l1;
#pragma unroll
    for (int t = 0; t < 24; t++) {
        st[t][0] *= inv0; st[t][1] *= inv0;
        st[t][2] *= inv1; st[t][3] *= inv1;
    }

    float o[8][4];
#pragma unroll
    for (int g = 0; g < 8; g++)
#pragma unroll
        for (int r = 0; r < 4; r++) o[g][r] = 0.f;

#pragma unroll
    for (int kk = 0; kk < 12; kk++) {
        unsigned a[4];
        a[0] = packf2h2(st[2 * kk][0],     st[2 * kk][1]);
        a[1] = packf2h2(st[2 * kk][2],     st[2 * kk][3]);
        a[2] = packf2h2(st[2 * kk + 1][0], st[2 * kk + 1][1]);
        a[3] = packf2h2(st[2 * kk + 1][2], st[2 * kk + 1][3]);
        int row = kk * 16 + (lane & 15);
#pragma unroll
        for (int g = 0; g < 4; g++) {
            unsigned bfr[4];
            int ch = 2 * g + (lane >> 4);
            ldsm_x4_t(bfr, sV + row * 128 + ((ch ^ (row & 7)) << 4));
            mma16816(o[2 * g],     a, &bfr[0]);
            mma16816(o[2 * g + 1], a, &bfr[2]);
        }
    }

#pragma unroll
    for (int g = 0; g < 8; g++) {
        int d = col0 + 8 * g + cj;
        *(__half2*)&Ch[(size_t)(qbase + r0) * D_MOD + d] =
            __floats2half2_rn(o[g][0], o[g][1]);
        *(__half2*)&Ch[(size_t)(qbase + r1) * D_MOD + d] =
            __floats2half2_rn(o[g][2], o[g][3]);
    }
}

// ---------------------------------------------------------------------------
extern "C" void kernel_launch(void* const* d_in, const int* in_sizes, int n_in,
                              void* d_out, int out_size) {
    const float* query = (const float*)d_in[0];
    const float* key   = (const float*)d_in[1];
    const float* value = (const float*)d_in[2];
    const float* Wq = (const float*)d_in[3];
    const float* bq = (const float*)d_in[4];
    const float* Wk = (const float*)d_in[5];
    const float* bk = (const float*)d_in[6];
    const float* Wv = (const float*)d_in[7];
    const float* bv = (const float*)d_in[8];
    const float* Wo = (const float*)d_in[9];
    const float* bo = (const float*)d_in[10];
    float* out = (float*)d_out;

    __half *qh, *kh, *vh, *ch, *ah, *wh;
    cudaGetSymbolAddress((void**)&qh, g_Qh);
    cudaGetSymbolAddress((void**)&kh, g_Kh);
    cudaGetSymbolAddress((void**)&vh, g_Vh);
    cudaGetSymbolAddress((void**)&ch, g_Ch);
    cudaGetSymbolAddress((void**)&ah, g_Ah);
    cudaGetSymbolAddress((void**)&wh, g_Wh);
    __half* ah0 = ah;
    __half* ah1 = ah + (size_t)S_LEN * D_MOD;
    __half* ah2 = ah + (size_t)2 * S_LEN * D_MOD;
    __half* wh0 = wh;
    __half* wh1 = wh + (size_t)D_MOD * D_MOD;
    __half* wh2 = wh + (size_t)2 * D_MOD * D_MOD;
    __half* wh3 = wh + (size_t)3 * D_MOD * D_MOD;

    const int gemm_smem2 = GSTAGES * 32768;   // NG=2: 96KB
    const int gemm_smem1 = GSTAGES * 24576;   // NG=1: 72KB
    cudaFuncSetAttribute((const void*)gemm_mma_kernel<2, true>,
                         cudaFuncAttributeMaxDynamicSharedMemorySize, gemm_smem2);
    cudaFuncSetAttribute((const void*)gemm_mma_kernel<1, false>,
                         cudaFuncAttributeMaxDynamicSharedMemorySize, gemm_smem1);
    cudaFuncSetAttribute(attn_kernel,
                         cudaFuncAttributeMaxDynamicSharedMemorySize, ATTN_SMEM);

    // ---- fused pack (all 7 arrays, one launch) ----
    pack_all_kernel<<<dim3(1536, 7), 256>>>(query, key, value, Wq, Wk, Wv, Wo,
                                            ah0, ah1, ah2, wh0, wh1, wh2, wh3);

    // ---- fused Q/K/V projections (NG=2, fp16 out) ----
    gemm_mma_kernel<2, true><<<dim3(6, 16, 3), 256, gemm_smem2>>>(
        ah0, ah1, ah2, wh0, wh1, wh2, bq, bk, bv,
        (float*)nullptr, (float*)nullptr, (float*)nullptr, qh, kh, vh);

    // ---- attention (fp16 in/out, HMMA) ----
    attn_kernel<<<dim3(S_LEN / QT, N_HEADS), 128, ATTN_SMEM>>>(qh, kh, vh, ch);

    // ---- output projection (NG=1 for full SM coverage, fp32 out) ----
    gemm_mma_kernel<1, false><<<dim3(12, 16, 1), 256, gemm_smem1>>>(
        ch, ch, ch, wh3, wh3, wh3, bo, bo, bo,
        out, out, out, (__half*)nullptr, (__half*)nullptr, (__half*)nullptr);
}